// round 12
// baseline (speedup 1.0000x reference)
#include <cuda_runtime.h>
#include <math.h>
#include <stdint.h>

#define BB 2
#define SEQ 2048
#define DMODEL 1024
#define NH 16
#define HD 64
#define QKV_ELEMS (BB * SEQ * DMODEL)

// Scratch (no allocations allowed)
__device__ float g_q[QKV_ELEMS];
__device__ float g_k[QKV_ELEMS];
__device__ float g_v[QKV_ELEMS];
__device__ float g_ctx[QKV_ELEMS];

__device__ __forceinline__ uint32_t f2tf(float x) {
    uint32_t r;
    asm("cvt.rna.tf32.f32 %0, %1;" : "=r"(r) : "f"(x));
    return r;
}

__device__ __forceinline__ void mma8(float* c, const uint32_t* a, const uint32_t* b) {
    asm volatile(
        "mma.sync.aligned.m16n8k8.row.col.f32.tf32.tf32.f32 "
        "{%0,%1,%2,%3},{%4,%5,%6,%7},{%8,%9},{%0,%1,%2,%3};"
        : "+f"(c[0]), "+f"(c[1]), "+f"(c[2]), "+f"(c[3])
        : "r"(a[0]), "r"(a[1]), "r"(a[2]), "r"(a[3]), "r"(b[0]), "r"(b[1]));
}

// ---------------------------------------------------------------------------
// Proj GEMM (NN): C[M,N] = A[M,K] @ B[K,N] + bias[N]  (R3 version, measured)
// ---------------------------------------------------------------------------
__global__ __launch_bounds__(256) void proj_tf32(
    const float* __restrict__ A, const float* __restrict__ B,
    const float* __restrict__ bias, float* __restrict__ C,
    int M, int N, int K)
{
    __shared__ uint32_t As[128][20];
    __shared__ uint32_t Bs[16][136];

    const int tid = threadIdx.x;
    const int lane = tid & 31, wid = tid >> 5;
    const int rowBase = blockIdx.y * 128, colBase = blockIdx.x * 128;
    const int rowOff = (wid >> 1) * 32, colOff = (wid & 1) * 64;
    const int gp = lane >> 2, tig = lane & 3;

    const int ar0 = tid >> 2, ac4 = tid & 3;
    const int bk0 = tid >> 5, bn4 = tid & 31;

    const float* Abase = A + (size_t)rowBase * K;

    float4 aPre[2], bPre[2];
    aPre[0] = *(const float4*)(Abase + (size_t)ar0 * K + ac4 * 4);
    aPre[1] = *(const float4*)(Abase + (size_t)(ar0 + 64) * K + ac4 * 4);
    bPre[0] = *(const float4*)(B + (size_t)bk0 * N + colBase + bn4 * 4);
    bPre[1] = *(const float4*)(B + (size_t)(bk0 + 8) * N + colBase + bn4 * 4);

    float acc[2][8][4];
#pragma unroll
    for (int t = 0; t < 2; t++)
#pragma unroll
        for (int j = 0; j < 8; j++)
#pragma unroll
            for (int q = 0; q < 4; q++) acc[t][j][q] = 0.0f;

    const int KT = K / 16;
    for (int kt = 0; kt < KT; ++kt) {
        As[ar0][ac4 * 4 + 0] = f2tf(aPre[0].x);
        As[ar0][ac4 * 4 + 1] = f2tf(aPre[0].y);
        As[ar0][ac4 * 4 + 2] = f2tf(aPre[0].z);
        As[ar0][ac4 * 4 + 3] = f2tf(aPre[0].w);
        As[ar0 + 64][ac4 * 4 + 0] = f2tf(aPre[1].x);
        As[ar0 + 64][ac4 * 4 + 1] = f2tf(aPre[1].y);
        As[ar0 + 64][ac4 * 4 + 2] = f2tf(aPre[1].z);
        As[ar0 + 64][ac4 * 4 + 3] = f2tf(aPre[1].w);
        Bs[bk0][bn4 * 4 + 0] = f2tf(bPre[0].x);
        Bs[bk0][bn4 * 4 + 1] = f2tf(bPre[0].y);
        Bs[bk0][bn4 * 4 + 2] = f2tf(bPre[0].z);
        Bs[bk0][bn4 * 4 + 3] = f2tf(bPre[0].w);
        Bs[bk0 + 8][bn4 * 4 + 0] = f2tf(bPre[1].x);
        Bs[bk0 + 8][bn4 * 4 + 1] = f2tf(bPre[1].y);
        Bs[bk0 + 8][bn4 * 4 + 2] = f2tf(bPre[1].z);
        Bs[bk0 + 8][bn4 * 4 + 3] = f2tf(bPre[1].w);
        __syncthreads();

        if (kt + 1 < KT) {
            const float* Ak = Abase + (kt + 1) * 16;
            aPre[0] = *(const float4*)(Ak + (size_t)ar0 * K + ac4 * 4);
            aPre[1] = *(const float4*)(Ak + (size_t)(ar0 + 64) * K + ac4 * 4);
            bPre[0] = *(const float4*)(B + (size_t)((kt + 1) * 16 + bk0) * N + colBase + bn4 * 4);
            bPre[1] = *(const float4*)(B + (size_t)((kt + 1) * 16 + bk0 + 8) * N + colBase + bn4 * 4);
        }

#pragma unroll
        for (int ks = 0; ks < 2; ++ks) {
            uint32_t a[2][4];
#pragma unroll
            for (int t = 0; t < 2; t++) {
                int r = rowOff + t * 16 + gp;
                a[t][0] = As[r][ks * 8 + tig];
                a[t][1] = As[r + 8][ks * 8 + tig];
                a[t][2] = As[r][ks * 8 + tig + 4];
                a[t][3] = As[r + 8][ks * 8 + tig + 4];
            }
#pragma unroll
            for (int j = 0; j < 8; j++) {
                uint32_t b[2];
                int cb = colOff + j * 8 + gp;
                b[0] = Bs[ks * 8 + tig][cb];
                b[1] = Bs[ks * 8 + tig + 4][cb];
                mma8(acc[0][j], a[0], b);
                mma8(acc[1][j], a[1], b);
            }
        }
        __syncthreads();
    }

#pragma unroll
    for (int t = 0; t < 2; t++) {
#pragma unroll
        for (int j = 0; j < 8; j++) {
            int row = rowBase + rowOff + t * 16 + gp;
            int col = colBase + colOff + j * 8 + 2 * tig;
            float2 bb = *(const float2*)&bias[col];
            float2 r0, r1;
            r0.x = acc[t][j][0] + bb.x; r0.y = acc[t][j][1] + bb.y;
            r1.x = acc[t][j][2] + bb.x; r1.y = acc[t][j][3] + bb.y;
            *(float2*)&C[(size_t)row * N + col] = r0;
            *(float2*)&C[(size_t)(row + 8) * N + col] = r1;
        }
    }
}

// ---------------------------------------------------------------------------
// attn_fused v2 with fragment pair-packing.
// Column permutation within each 8-col block: col c = ks*8+t (t in 0..7)
//   -> pcol = ks*8 + 2*(t&3) + (t>>2)
// so fragment pairs (c, c+4) are ADJACENT -> LDS.64 loads.
// Row strides chosen == 8 mod 32 for conflict-free paired loads.
// ---------------------------------------------------------------------------
#define QKSTRIDE 72     // phase-1 Q/K rows (uint32), 72 % 32 == 8
#define CPSTRIDE 40     // phase-2 P rows, 40 % 32 == 8
#define CVSTRIDE 72     // phase-2 V rows (k-major, scalar b loads)
__global__ __launch_bounds__(256, 2) void attn_fused(float* __restrict__ attn)
{
    extern __shared__ uint32_t smr[];
    uint32_t* Qs = smr;                                // phase1 [128][72]
    uint32_t* Ks = smr + 128 * QKSTRIDE;               // phase1 [128][72]
    float* sm_m = (float*)(smr + 2 * 128 * QKSTRIDE);  // [128]
    float* sm_l = sm_m + 128;                          // [128]
    uint32_t* Ps = smr;                                // phase2 [128][40] (reuse)
    uint32_t* Vs = smr + 128 * CPSTRIDE;               // phase2 [32][72]  (reuse)

    const int tid = threadIdx.x;
    const int lane = tid & 31, wid = tid >> 5;
    const int warpM = wid >> 1, warpN = wid & 1;
    const int gp = lane >> 2, tig = lane & 3;
    const int z = blockIdx.y, b = z >> 4, h = z & 15;
    const int rowBase = blockIdx.x * 128;

    const float* Qb = g_q + (size_t)(b * SEQ) * DMODEL + h * HD;
    const float* Kb = g_k + (size_t)(b * SEQ) * DMODEL + h * HD;
    float* Sbase = attn + (size_t)z * SEQ * SEQ;

    // ---------------- Phase 1: scores + stats ----------------
    // stage Q scaled, permuted: thread g covers row r=g>>4, cols c4*4..c4*4+3
    // c4 even -> slots ks*8 + {0,2,4,6}; c4 odd -> ks*8 + {1,3,5,7}
#pragma unroll
    for (int i = 0; i < 8; i++) {
        int g = tid + i * 256;
        int r = g >> 4, c4 = g & 15;
        int base = r * QKSTRIDE + (c4 >> 1) * 8 + (c4 & 1);
        float4 qv = *(const float4*)(Qb + (size_t)(rowBase + r) * DMODEL + c4 * 4);
        Qs[base + 0] = f2tf(qv.x * 0.125f);
        Qs[base + 2] = f2tf(qv.y * 0.125f);
        Qs[base + 4] = f2tf(qv.z * 0.125f);
        Qs[base + 6] = f2tf(qv.w * 0.125f);
    }

    float mP[2][2], lP[2][2];
#pragma unroll
    for (int t = 0; t < 2; t++)
#pragma unroll
        for (int hf = 0; hf < 2; hf++) { mP[t][hf] = -1e30f; lP[t][hf] = 0.0f; }

    for (int kc = 0; kc < 16; ++kc) {
        __syncthreads();
#pragma unroll
        for (int i = 0; i < 8; i++) {
            int g = tid + i * 256;
            int r = g >> 4, c4 = g & 15;
            int base = r * QKSTRIDE + (c4 >> 1) * 8 + (c4 & 1);
            float4 kv = *(const float4*)(Kb + (size_t)(kc * 128 + r) * DMODEL + c4 * 4);
            Ks[base + 0] = f2tf(kv.x);
            Ks[base + 2] = f2tf(kv.y);
            Ks[base + 4] = f2tf(kv.z);
            Ks[base + 6] = f2tf(kv.w);
        }
        __syncthreads();

        float acc[2][8][4];
#pragma unroll
        for (int t = 0; t < 2; t++)
#pragma unroll
            for (int j = 0; j < 8; j++)
#pragma unroll
                for (int q = 0; q < 4; q++) acc[t][j][q] = 0.0f;

#pragma unroll
        for (int ks = 0; ks < 8; ++ks) {
            uint32_t a[2][4];
#pragma unroll
            for (int t = 0; t < 2; t++) {
                int r = warpM * 32 + t * 16 + gp;
                uint2 lo = *(const uint2*)&Qs[r * QKSTRIDE + ks * 8 + 2 * tig];
                uint2 hi = *(const uint2*)&Qs[(r + 8) * QKSTRIDE + ks * 8 + 2 * tig];
                a[t][0] = lo.x; a[t][2] = lo.y;
                a[t][1] = hi.x; a[t][3] = hi.y;
            }
#pragma unroll
            for (int j = 0; j < 8; j++) {
                int n = warpN * 64 + j * 8 + gp;
                uint2 bp = *(const uint2*)&Ks[n * QKSTRIDE + ks * 8 + 2 * tig];
                uint32_t b2[2] = { bp.x, bp.y };
                mma8(acc[0][j], a[0], b2);
                mma8(acc[1][j], a[1], b2);
            }
        }

#pragma unroll
        for (int t = 0; t < 2; t++) {
            float tm0 = -1e30f, tm1 = -1e30f;
#pragma unroll
            for (int j = 0; j < 8; j++) {
                tm0 = fmaxf(tm0, fmaxf(acc[t][j][0], acc[t][j][1]));
                tm1 = fmaxf(tm1, fmaxf(acc[t][j][2], acc[t][j][3]));
            }
            tm0 = fmaxf(tm0, __shfl_xor_sync(0xffffffffu, tm0, 1));
            tm0 = fmaxf(tm0, __shfl_xor_sync(0xffffffffu, tm0, 2));
            tm1 = fmaxf(tm1, __shfl_xor_sync(0xffffffffu, tm1, 1));
            tm1 = fmaxf(tm1, __shfl_xor_sync(0xffffffffu, tm1, 2));
            float mn0 = fmaxf(mP[t][0], tm0), mn1 = fmaxf(mP[t][1], tm1);
            float ts0 = 0.0f, ts1 = 0.0f;
#pragma unroll
            for (int j = 0; j < 8; j++) {
                ts0 += expf(acc[t][j][0] - mn0) + expf(acc[t][j][1] - mn0);
                ts1 += expf(acc[t][j][2] - mn1) + expf(acc[t][j][3] - mn1);
            }
            ts0 += __shfl_xor_sync(0xffffffffu, ts0, 1);
            ts0 += __shfl_xor_sync(0xffffffffu, ts0, 2);
            ts1 += __shfl_xor_sync(0xffffffffu, ts1, 1);
            ts1 += __shfl_xor_sync(0xffffffffu, ts1, 2);
            lP[t][0] = lP[t][0] * expf(mP[t][0] - mn0) + ts0; mP[t][0] = mn0;
            lP[t][1] = lP[t][1] * expf(mP[t][1] - mn1) + ts1; mP[t][1] = mn1;
        }

#pragma unroll
        for (int t = 0; t < 2; t++) {
            int rowg = rowBase + warpM * 32 + t * 16 + gp;
            float* Crow0 = Sbase + (size_t)rowg * SEQ + kc * 128 + warpN * 64;
            float* Crow1 = Crow0 + (size_t)8 * SEQ;
#pragma unroll
            for (int j = 0; j < 8; j++) {
                float2 v0, v1;
                v0.x = acc[t][j][0]; v0.y = acc[t][j][1];
                v1.x = acc[t][j][2]; v1.y = acc[t][j][3];
                *(float2*)(Crow0 + j * 8 + 2 * tig) = v0;
                *(float2*)(Crow1 + j * 8 + 2 * tig) = v1;
            }
        }
    }

    // stats merge across warpN pair (into smem)
    __syncthreads();
    if (warpN == 1 && tig == 0) {
#pragma unroll
        for (int t = 0; t < 2; t++)
#pragma unroll
            for (int hf = 0; hf < 2; hf++) {
                int rl = warpM * 32 + t * 16 + hf * 8 + gp;
                sm_m[rl] = mP[t][hf];
                sm_l[rl] = lP[t][hf];
            }
    }
    __syncthreads();
    if (warpN == 0 && tig == 0) {
#pragma unroll
        for (int t = 0; t < 2; t++)
#pragma unroll
            for (int hf = 0; hf < 2; hf++) {
                int rl = warpM * 32 + t * 16 + hf * 8 + gp;
                float ma = mP[t][hf], la = lP[t][hf];
                float mb = sm_m[rl],  lb = sm_l[rl];
                float mf = fmaxf(ma, mb);
                sm_m[rl] = mf;
                sm_l[rl] = la * expf(ma - mf) + lb * expf(mb - mf);
            }
    }
    __syncthreads();

    // ---------------- Phase 2: normalize + ctx ----------------
    const float* V = g_v + (size_t)b * SEQ * DMODEL + h * HD;

    float mR[4], ilR[4];
#pragma unroll
    for (int i = 0; i < 4; i++) {
        int r = (tid + i * 256) >> 3;
        mR[i]  = sm_m[r];
        ilR[i] = 1.0f / sm_l[r];
    }

    float acc2[2][4][4];
#pragma unroll
    for (int t = 0; t < 2; t++)
#pragma unroll
        for (int j = 0; j < 4; j++)
#pragma unroll
            for (int q = 0; q < 4; q++) acc2[t][j][q] = 0.0f;

    float4 pPre[4], vPre[2];
#pragma unroll
    for (int i = 0; i < 4; i++) {
        int g = tid + i * 256;
        int r = g >> 3, c4 = g & 7;
        pPre[i] = *(const float4*)(Sbase + (size_t)(rowBase + r) * SEQ + c4 * 4);
    }
#pragma unroll
    for (int i = 0; i < 2; i++) {
        int g = tid + i * 256;
        int k = g >> 4, n4 = g & 15;
        vPre[i] = *(const float4*)(V + (size_t)k * DMODEL + n4 * 4);
    }

    const int KT = SEQ / 32;
    for (int kt = 0; kt < KT; ++kt) {
#pragma unroll
        for (int i = 0; i < 4; i++) {
            int g = tid + i * 256;
            int r = g >> 3, c4 = g & 7;
            float4 v = pPre[i];
            float4 p;
            p.x = expf(v.x - mR[i]) * ilR[i];
            p.y = expf(v.y - mR[i]) * ilR[i];
            p.z = expf(v.z - mR[i]) * ilR[i];
            p.w = expf(v.w - mR[i]) * ilR[i];
            *(float4*)(Sbase + (size_t)(rowBase + r) * SEQ + kt * 32 + c4 * 4) = p;
            int base = r * CPSTRIDE + (c4 >> 1) * 8 + (c4 & 1);
            Ps[base + 0] = f2tf(p.x);
            Ps[base + 2] = f2tf(p.y);
            Ps[base + 4] = f2tf(p.z);
            Ps[base + 6] = f2tf(p.w);
        }
#pragma unroll
        for (int i = 0; i < 2; i++) {
            int g = tid + i * 256;
            int k = g >> 4, n4 = g & 15;
            uint32_t* vp = &Vs[k * CVSTRIDE + n4 * 4];
            vp[0] = f2tf(vPre[i].x); vp[1] = f2tf(vPre[i].y);
            vp[2] = f2tf(vPre[i].z); vp[3] = f2tf(vPre[i].w);
        }
        __syncthreads();

        if (kt + 1 < KT) {
#pragma unroll
            for (int i = 0; i < 4; i++) {
                int g = tid + i * 256;
                int r = g >> 3, c4 = g & 7;
                pPre[i] = *(const float4*)(Sbase + (size_t)(rowBase + r) * SEQ + (kt + 1) * 32 + c4 * 4);
            }
#pragma unroll
            for (int i = 0; i < 2; i++) {
                int g = tid + i * 256;
                int k = g >> 4, n4 = g & 15;
                vPre[i] = *(const float4*)(V + (size_t)((kt + 1) * 32 + k) * DMODEL + n4 * 4);
            }
        }

#pragma unroll
        for (int ks = 0; ks < 4; ++ks) {
            uint32_t a[2][4];
#pragma unroll
            for (int t = 0; t < 2; t++) {
                int r = warpM * 32 + t * 16 + gp;
                uint2 lo = *(const uint2*)&Ps[r * CPSTRIDE + ks * 8 + 2 * tig];
                uint2 hi = *(const uint2*)&Ps[(r + 8) * CPSTRIDE + ks * 8 + 2 * tig];
                a[t][0] = lo.x; a[t][2] = lo.y;
                a[t][1] = hi.x; a[t][3] = hi.y;
            }
#pragma unroll
            for (int j = 0; j < 4; j++) {
                uint32_t b2[2];
                int cb = warpN * 32 + j * 8 + gp;
                b2[0] = Vs[(ks * 8 + tig) * CVSTRIDE + cb];
                b2[1] = Vs[(ks * 8 + tig + 4) * CVSTRIDE + cb];
                mma8(acc2[0][j], a[0], b2);
                mma8(acc2[1][j], a[1], b2);
            }
        }
        __syncthreads();
    }

#pragma unroll
    for (int t = 0; t < 2; t++) {
#pragma unroll
        for (int j = 0; j < 4; j++) {
            int row = rowBase + warpM * 32 + t * 16 + gp;
            int col = warpN * 32 + j * 8 + 2 * tig;
            float* dst0 = g_ctx + (size_t)(b * SEQ + row) * DMODEL + h * HD + col;
            float* dst1 = g_ctx + (size_t)(b * SEQ + row + 8) * DMODEL + h * HD + col;
            float2 r0, r1;
            r0.x = acc2[t][j][0]; r0.y = acc2[t][j][1];
            r1.x = acc2[t][j][2]; r1.y = acc2[t][j][3];
            *(float2*)dst0 = r0;
            *(float2*)dst1 = r1;
        }
    }
}

// ---------------------------------------------------------------------------
extern "C" void kernel_launch(void* const* d_in, const int* in_sizes, int n_in,
                              void* d_out, int out_size)
{
    const float* inputs_q  = (const float*)d_in[0];
    const float* inputs_kv = (const float*)d_in[1];
    const float* Wq = (const float*)d_in[2];
    const float* bq = (const float*)d_in[3];
    const float* Wk = (const float*)d_in[4];
    const float* bk = (const float*)d_in[5];
    const float* Wv = (const float*)d_in[6];
    const float* bv = (const float*)d_in[7];
    const float* Wo = (const float*)d_in[8];
    const float* bo = (const float*)d_in[9];

    float* out  = (float*)d_out;                       // [B,SQ,D]
    float* attn = out + (size_t)BB * SEQ * DMODEL;     // [B,H,SQ,SKV]

    float *q, *k, *v, *ctx;
    cudaGetSymbolAddress((void**)&q,   g_q);
    cudaGetSymbolAddress((void**)&k,   g_k);
    cudaGetSymbolAddress((void**)&v,   g_v);
    cudaGetSymbolAddress((void**)&ctx, g_ctx);

    const int SMEMA = (2 * 128 * QKSTRIDE + 256) * 4;  // Qs+Ks (reused) + stats, ~73KB
    cudaFuncSetAttribute(attn_fused, cudaFuncAttributeMaxDynamicSharedMemorySize, SMEMA);

    dim3 gProj(DMODEL / 128, (BB * SEQ) / 128);        // (8, 32)

    proj_tf32<<<gProj, 256>>>(inputs_q,  Wq, bq, q, BB * SEQ, DMODEL, DMODEL);
    proj_tf32<<<gProj, 256>>>(inputs_kv, Wk, bk, k, BB * SEQ, DMODEL, DMODEL);
    proj_tf32<<<gProj, 256>>>(inputs_kv, Wv, bv, v, BB * SEQ, DMODEL, DMODEL);

    attn_fused<<<dim3(SEQ / 128, BB * NH), 256, SMEMA>>>(attn);

    proj_tf32<<<gProj, 256>>>(ctx, Wo, bo, out, BB * SEQ, DMODEL, DMODEL);
}

// round 13
// speedup vs baseline: 1.1042x; 1.1042x over previous
#include <cuda_runtime.h>
#include <math.h>
#include <stdint.h>

#define BB 2
#define SEQ 2048
#define DMODEL 1024
#define NH 16
#define HD 64
#define QKV_ELEMS (BB * SEQ * DMODEL)

// Scratch (no allocations allowed)
__device__ float g_q[QKV_ELEMS];
__device__ float g_k[QKV_ELEMS];
__device__ float g_v[QKV_ELEMS];
__device__ float g_ctx[QKV_ELEMS];
__device__ float g_m[BB * NH * SEQ];
__device__ float g_l[BB * NH * SEQ];

__device__ __forceinline__ uint32_t f2tf(float x) {
    uint32_t r;
    asm("cvt.rna.tf32.f32 %0, %1;" : "=r"(r) : "f"(x));
    return r;
}

__device__ __forceinline__ void mma8(float* c, const uint32_t* a, const uint32_t* b) {
    asm volatile(
        "mma.sync.aligned.m16n8k8.row.col.f32.tf32.tf32.f32 "
        "{%0,%1,%2,%3},{%4,%5,%6,%7},{%8,%9},{%0,%1,%2,%3};"
        : "+f"(c[0]), "+f"(c[1]), "+f"(c[2]), "+f"(c[3])
        : "r"(a[0]), "r"(a[1]), "r"(a[2]), "r"(a[3]), "r"(b[0]), "r"(b[1]));
}

// ---------------------------------------------------------------------------
// Proj GEMM (NN): C[M,N] = A[M,K] @ B[K,N] + bias[N]
// R3 structure + occupancy 2 (regs capped at 128).
// ---------------------------------------------------------------------------
__global__ __launch_bounds__(256, 2) void proj_tf32(
    const float* __restrict__ A, const float* __restrict__ B,
    const float* __restrict__ bias, float* __restrict__ C,
    int M, int N, int K)
{
    __shared__ uint32_t As[128][20];
    __shared__ uint32_t Bs[16][136];

    const int tid = threadIdx.x;
    const int lane = tid & 31, wid = tid >> 5;
    const int rowBase = blockIdx.y * 128, colBase = blockIdx.x * 128;
    const int rowOff = (wid >> 1) * 32, colOff = (wid & 1) * 64;
    const int gp = lane >> 2, tig = lane & 3;

    const int ar0 = tid >> 2, ac4 = tid & 3;
    const int bk0 = tid >> 5, bn4 = tid & 31;

    const float* Abase = A + (size_t)rowBase * K;

    float4 aPre[2], bPre[2];
    aPre[0] = *(const float4*)(Abase + (size_t)ar0 * K + ac4 * 4);
    aPre[1] = *(const float4*)(Abase + (size_t)(ar0 + 64) * K + ac4 * 4);
    bPre[0] = *(const float4*)(B + (size_t)bk0 * N + colBase + bn4 * 4);
    bPre[1] = *(const float4*)(B + (size_t)(bk0 + 8) * N + colBase + bn4 * 4);

    float acc[2][8][4];
#pragma unroll
    for (int t = 0; t < 2; t++)
#pragma unroll
        for (int j = 0; j < 8; j++)
#pragma unroll
            for (int q = 0; q < 4; q++) acc[t][j][q] = 0.0f;

    const int KT = K / 16;
    for (int kt = 0; kt < KT; ++kt) {
        As[ar0][ac4 * 4 + 0] = f2tf(aPre[0].x);
        As[ar0][ac4 * 4 + 1] = f2tf(aPre[0].y);
        As[ar0][ac4 * 4 + 2] = f2tf(aPre[0].z);
        As[ar0][ac4 * 4 + 3] = f2tf(aPre[0].w);
        As[ar0 + 64][ac4 * 4 + 0] = f2tf(aPre[1].x);
        As[ar0 + 64][ac4 * 4 + 1] = f2tf(aPre[1].y);
        As[ar0 + 64][ac4 * 4 + 2] = f2tf(aPre[1].z);
        As[ar0 + 64][ac4 * 4 + 3] = f2tf(aPre[1].w);
        Bs[bk0][bn4 * 4 + 0] = f2tf(bPre[0].x);
        Bs[bk0][bn4 * 4 + 1] = f2tf(bPre[0].y);
        Bs[bk0][bn4 * 4 + 2] = f2tf(bPre[0].z);
        Bs[bk0][bn4 * 4 + 3] = f2tf(bPre[0].w);
        Bs[bk0 + 8][bn4 * 4 + 0] = f2tf(bPre[1].x);
        Bs[bk0 + 8][bn4 * 4 + 1] = f2tf(bPre[1].y);
        Bs[bk0 + 8][bn4 * 4 + 2] = f2tf(bPre[1].z);
        Bs[bk0 + 8][bn4 * 4 + 3] = f2tf(bPre[1].w);
        __syncthreads();

        if (kt + 1 < KT) {
            const float* Ak = Abase + (kt + 1) * 16;
            aPre[0] = *(const float4*)(Ak + (size_t)ar0 * K + ac4 * 4);
            aPre[1] = *(const float4*)(Ak + (size_t)(ar0 + 64) * K + ac4 * 4);
            bPre[0] = *(const float4*)(B + (size_t)((kt + 1) * 16 + bk0) * N + colBase + bn4 * 4);
            bPre[1] = *(const float4*)(B + (size_t)((kt + 1) * 16 + bk0 + 8) * N + colBase + bn4 * 4);
        }

#pragma unroll
        for (int ks = 0; ks < 2; ++ks) {
            uint32_t a[2][4];
#pragma unroll
            for (int t = 0; t < 2; t++) {
                int r = rowOff + t * 16 + gp;
                a[t][0] = As[r][ks * 8 + tig];
                a[t][1] = As[r + 8][ks * 8 + tig];
                a[t][2] = As[r][ks * 8 + tig + 4];
                a[t][3] = As[r + 8][ks * 8 + tig + 4];
            }
#pragma unroll
            for (int j = 0; j < 8; j++) {
                uint32_t b[2];
                int cb = colOff + j * 8 + gp;
                b[0] = Bs[ks * 8 + tig][cb];
                b[1] = Bs[ks * 8 + tig + 4][cb];
                mma8(acc[0][j], a[0], b);
                mma8(acc[1][j], a[1], b);
            }
        }
        __syncthreads();
    }

#pragma unroll
    for (int t = 0; t < 2; t++) {
#pragma unroll
        for (int j = 0; j < 8; j++) {
            int row = rowBase + rowOff + t * 16 + gp;
            int col = colBase + colOff + j * 8 + 2 * tig;
            float2 bb = *(const float2*)&bias[col];
            float2 r0, r1;
            r0.x = acc[t][j][0] + bb.x; r0.y = acc[t][j][1] + bb.y;
            r1.x = acc[t][j][2] + bb.x; r1.y = acc[t][j][3] + bb.y;
            *(float2*)&C[(size_t)row * N + col] = r0;
            *(float2*)&C[(size_t)(row + 8) * N + col] = r1;
        }
    }
}

// ---------------------------------------------------------------------------
// scores_stats v3 (R10, measured 189us): warp tile 32x64, per-warp partial
// online stats, cross-warp merge via smem. Raw S -> attn; stats -> g_m/g_l.
// ---------------------------------------------------------------------------
#define SSTRIDE 68
__global__ __launch_bounds__(256, 2) void scores_stats(float* __restrict__ attn)
{
    extern __shared__ uint32_t sm1[];
    uint32_t* Qs = sm1;                           // [128][68]
    uint32_t* Ks = sm1 + 128 * SSTRIDE;           // [128][68]
    float* sm_m = (float*)(sm1 + 2 * 128 * SSTRIDE);   // [128]
    float* sm_l = sm_m + 128;                          // [128]

    const int tid = threadIdx.x;
    const int lane = tid & 31, wid = tid >> 5;
    const int warpM = wid >> 1, warpN = wid & 1;
    const int gp = lane >> 2, tig = lane & 3;
    const int z = blockIdx.y, b = z >> 4, h = z & 15;
    const int rowBase = blockIdx.x * 128;

    const float* Qb = g_q + (size_t)(b * SEQ) * DMODEL + h * HD;
    const float* Kb = g_k + (size_t)(b * SEQ) * DMODEL + h * HD;

#pragma unroll
    for (int i = 0; i < 8; i++) {
        int g = tid + i * 256;
        int r = g >> 4, c4 = g & 15;
        float4 qv = *(const float4*)(Qb + (size_t)(rowBase + r) * DMODEL + c4 * 4);
        uint32_t* qp = &Qs[r * SSTRIDE + c4 * 4];
        qp[0] = f2tf(qv.x * 0.125f); qp[1] = f2tf(qv.y * 0.125f);
        qp[2] = f2tf(qv.z * 0.125f); qp[3] = f2tf(qv.w * 0.125f);
    }

    float mP[2][2], lP[2][2];
#pragma unroll
    for (int t = 0; t < 2; t++)
#pragma unroll
        for (int hf = 0; hf < 2; hf++) { mP[t][hf] = -1e30f; lP[t][hf] = 0.0f; }

    for (int kc = 0; kc < 16; ++kc) {
        __syncthreads();
#pragma unroll
        for (int i = 0; i < 8; i++) {
            int g = tid + i * 256;
            int r = g >> 4, c4 = g & 15;
            float4 kv = *(const float4*)(Kb + (size_t)(kc * 128 + r) * DMODEL + c4 * 4);
            uint32_t* kp = &Ks[r * SSTRIDE + c4 * 4];
            kp[0] = f2tf(kv.x); kp[1] = f2tf(kv.y);
            kp[2] = f2tf(kv.z); kp[3] = f2tf(kv.w);
        }
        __syncthreads();

        float acc[2][8][4];
#pragma unroll
        for (int t = 0; t < 2; t++)
#pragma unroll
            for (int j = 0; j < 8; j++)
#pragma unroll
                for (int q = 0; q < 4; q++) acc[t][j][q] = 0.0f;

#pragma unroll
        for (int ks = 0; ks < 8; ++ks) {
            uint32_t a[2][4];
#pragma unroll
            for (int t = 0; t < 2; t++) {
                int r = warpM * 32 + t * 16 + gp;
                a[t][0] = Qs[r * SSTRIDE + ks * 8 + tig];
                a[t][1] = Qs[(r + 8) * SSTRIDE + ks * 8 + tig];
                a[t][2] = Qs[r * SSTRIDE + ks * 8 + tig + 4];
                a[t][3] = Qs[(r + 8) * SSTRIDE + ks * 8 + tig + 4];
            }
#pragma unroll
            for (int j = 0; j < 8; j++) {
                uint32_t b2[2];
                int n = warpN * 64 + j * 8 + gp;
                b2[0] = Ks[n * SSTRIDE + ks * 8 + tig];
                b2[1] = Ks[n * SSTRIDE + ks * 8 + tig + 4];
                mma8(acc[0][j], a[0], b2);
                mma8(acc[1][j], a[1], b2);
            }
        }

#pragma unroll
        for (int t = 0; t < 2; t++) {
            float tm0 = -1e30f, tm1 = -1e30f;
#pragma unroll
            for (int j = 0; j < 8; j++) {
                tm0 = fmaxf(tm0, fmaxf(acc[t][j][0], acc[t][j][1]));
                tm1 = fmaxf(tm1, fmaxf(acc[t][j][2], acc[t][j][3]));
            }
            tm0 = fmaxf(tm0, __shfl_xor_sync(0xffffffffu, tm0, 1));
            tm0 = fmaxf(tm0, __shfl_xor_sync(0xffffffffu, tm0, 2));
            tm1 = fmaxf(tm1, __shfl_xor_sync(0xffffffffu, tm1, 1));
            tm1 = fmaxf(tm1, __shfl_xor_sync(0xffffffffu, tm1, 2));
            float mn0 = fmaxf(mP[t][0], tm0), mn1 = fmaxf(mP[t][1], tm1);
            float ts0 = 0.0f, ts1 = 0.0f;
#pragma unroll
            for (int j = 0; j < 8; j++) {
                ts0 += expf(acc[t][j][0] - mn0) + expf(acc[t][j][1] - mn0);
                ts1 += expf(acc[t][j][2] - mn1) + expf(acc[t][j][3] - mn1);
            }
            ts0 += __shfl_xor_sync(0xffffffffu, ts0, 1);
            ts0 += __shfl_xor_sync(0xffffffffu, ts0, 2);
            ts1 += __shfl_xor_sync(0xffffffffu, ts1, 1);
            ts1 += __shfl_xor_sync(0xffffffffu, ts1, 2);
            lP[t][0] = lP[t][0] * expf(mP[t][0] - mn0) + ts0; mP[t][0] = mn0;
            lP[t][1] = lP[t][1] * expf(mP[t][1] - mn1) + ts1; mP[t][1] = mn1;
        }

#pragma unroll
        for (int t = 0; t < 2; t++) {
            int rowg = rowBase + warpM * 32 + t * 16 + gp;
            float* Crow0 = attn + (size_t)z * SEQ * SEQ + (size_t)rowg * SEQ + kc * 128 + warpN * 64;
            float* Crow1 = Crow0 + (size_t)8 * SEQ;
#pragma unroll
            for (int j = 0; j < 8; j++) {
                float2 v0, v1;
                v0.x = acc[t][j][0]; v0.y = acc[t][j][1];
                v1.x = acc[t][j][2]; v1.y = acc[t][j][3];
                *(float2*)(Crow0 + j * 8 + 2 * tig) = v0;
                *(float2*)(Crow1 + j * 8 + 2 * tig) = v1;
            }
        }
    }

    __syncthreads();
    if (warpN == 1 && tig == 0) {
#pragma unroll
        for (int t = 0; t < 2; t++)
#pragma unroll
            for (int hf = 0; hf < 2; hf++) {
                int rl = warpM * 32 + t * 16 + hf * 8 + gp;
                sm_m[rl] = mP[t][hf];
                sm_l[rl] = lP[t][hf];
            }
    }
    __syncthreads();
    if (warpN == 0 && tig == 0) {
#pragma unroll
        for (int t = 0; t < 2; t++)
#pragma unroll
            for (int hf = 0; hf < 2; hf++) {
                int rl = warpM * 32 + t * 16 + hf * 8 + gp;
                float ma = mP[t][hf], la = lP[t][hf];
                float mb = sm_m[rl],  lb = sm_l[rl];
                float mf = fmaxf(ma, mb);
                float lf = la * expf(ma - mf) + lb * expf(mb - mf);
                g_m[(size_t)z * SEQ + rowBase + rl] = mf;
                g_l[(size_t)z * SEQ + rowBase + rl] = lf;
            }
    }
}

// ---------------------------------------------------------------------------
// ctx_fused2 (R9/R10, measured): reads raw S, p = exp(s-m)*il, writes
// normalized P back (attn output), ctx += P @ V.
// ---------------------------------------------------------------------------
__global__ __launch_bounds__(256, 2) void ctx_fused2(float* __restrict__ attn)
{
    __shared__ uint32_t Ps[128][36];
    __shared__ uint32_t Vs[32][72];

    const int tid = threadIdx.x;
    const int lane = tid & 31, wid = tid >> 5;
    const int warpM = wid >> 1, warpN = wid & 1;
    const int gp = lane >> 2, tig = lane & 3;
    const int z = blockIdx.y, b = z >> 4, h = z & 15;
    const int rowBase = blockIdx.x * 128;

    float* P = attn + (size_t)z * SEQ * SEQ;
    const float* V = g_v + (size_t)b * SEQ * DMODEL + h * HD;

    float mR[4], ilR[4];
#pragma unroll
    for (int i = 0; i < 4; i++) {
        int r = (tid + i * 256) >> 3;
        mR[i]  = g_m[(size_t)z * SEQ + rowBase + r];
        ilR[i] = 1.0f / g_l[(size_t)z * SEQ + rowBase + r];
    }

    float acc[2][4][4];
#pragma unroll
    for (int t = 0; t < 2; t++)
#pragma unroll
        for (int j = 0; j < 4; j++)
#pragma unroll
            for (int q = 0; q < 4; q++) acc[t][j][q] = 0.0f;

    float4 pPre[4], vPre[2];
#pragma unroll
    for (int i = 0; i < 4; i++) {
        int g = tid + i * 256;
        int r = g >> 3, c4 = g & 7;
        pPre[i] = *(const float4*)(P + (size_t)(rowBase + r) * SEQ + c4 * 4);
    }
#pragma unroll
    for (int i = 0; i < 2; i++) {
        int g = tid + i * 256;
        int k = g >> 4, n4 = g & 15;
        vPre[i] = *(const float4*)(V + (size_t)k * DMODEL + n4 * 4);
    }

    const int KT = SEQ / 32;
    for (int kt = 0; kt < KT; ++kt) {
#pragma unroll
        for (int i = 0; i < 4; i++) {
            int g = tid + i * 256;
            int r = g >> 3, c4 = g & 7;
            float4 v = pPre[i];
            float4 p;
            p.x = expf(v.x - mR[i]) * ilR[i];
            p.y = expf(v.y - mR[i]) * ilR[i];
            p.z = expf(v.z - mR[i]) * ilR[i];
            p.w = expf(v.w - mR[i]) * ilR[i];
            *(float4*)(P + (size_t)(rowBase + r) * SEQ + kt * 32 + c4 * 4) = p;
            uint32_t* pp = &Ps[r][c4 * 4];
            pp[0] = f2tf(p.x); pp[1] = f2tf(p.y);
            pp[2] = f2tf(p.z); pp[3] = f2tf(p.w);
        }
#pragma unroll
        for (int i = 0; i < 2; i++) {
            int g = tid + i * 256;
            int k = g >> 4, n4 = g & 15;
            uint32_t* vp = &Vs[k][n4 * 4];
            vp[0] = f2tf(vPre[i].x); vp[1] = f2tf(vPre[i].y);
            vp[2] = f2tf(vPre[i].z); vp[3] = f2tf(vPre[i].w);
        }
        __syncthreads();

        if (kt + 1 < KT) {
#pragma unroll
            for (int i = 0; i < 4; i++) {
                int g = tid + i * 256;
                int r = g >> 3, c4 = g & 7;
                pPre[i] = *(const float4*)(P + (size_t)(rowBase + r) * SEQ + (kt + 1) * 32 + c4 * 4);
            }
#pragma unroll
            for (int i = 0; i < 2; i++) {
                int g = tid + i * 256;
                int k = g >> 4, n4 = g & 15;
                vPre[i] = *(const float4*)(V + (size_t)((kt + 1) * 32 + k) * DMODEL + n4 * 4);
            }
        }

#pragma unroll
        for (int ks = 0; ks < 4; ++ks) {
            uint32_t a[2][4];
#pragma unroll
            for (int t = 0; t < 2; t++) {
                int r = warpM * 32 + t * 16 + gp;
                a[t][0] = Ps[r][ks * 8 + tig];
                a[t][1] = Ps[r + 8][ks * 8 + tig];
                a[t][2] = Ps[r][ks * 8 + tig + 4];
                a[t][3] = Ps[r + 8][ks * 8 + tig + 4];
            }
#pragma unroll
            for (int j = 0; j < 4; j++) {
                uint32_t b2[2];
                int cb = warpN * 32 + j * 8 + gp;
                b2[0] = Vs[ks * 8 + tig][cb];
                b2[1] = Vs[ks * 8 + tig + 4][cb];
                mma8(acc[0][j], a[0], b2);
                mma8(acc[1][j], a[1], b2);
            }
        }
        __syncthreads();
    }

#pragma unroll
    for (int t = 0; t < 2; t++) {
#pragma unroll
        for (int j = 0; j < 4; j++) {
            int row = rowBase + warpM * 32 + t * 16 + gp;
            int col = warpN * 32 + j * 8 + 2 * tig;
            float* dst0 = g_ctx + (size_t)(b * SEQ + row) * DMODEL + h * HD + col;
            float* dst1 = g_ctx + (size_t)(b * SEQ + row + 8) * DMODEL + h * HD + col;
            float2 r0, r1;
            r0.x = acc[t][j][0]; r0.y = acc[t][j][1];
            r1.x = acc[t][j][2]; r1.y = acc[t][j][3];
            *(float2*)dst0 = r0;
            *(float2*)dst1 = r1;
        }
    }
}

// ---------------------------------------------------------------------------
extern "C" void kernel_launch(void* const* d_in, const int* in_sizes, int n_in,
                              void* d_out, int out_size)
{
    const float* inputs_q  = (const float*)d_in[0];
    const float* inputs_kv = (const float*)d_in[1];
    const float* Wq = (const float*)d_in[2];
    const float* bq = (const float*)d_in[3];
    const float* Wk = (const float*)d_in[4];
    const float* bk = (const float*)d_in[5];
    const float* Wv = (const float*)d_in[6];
    const float* bv = (const float*)d_in[7];
    const float* Wo = (const float*)d_in[8];
    const float* bo = (const float*)d_in[9];

    float* out  = (float*)d_out;                       // [B,SQ,D]
    float* attn = out + (size_t)BB * SEQ * DMODEL;     // [B,H,SQ,SKV]

    float *q, *k, *v, *ctx;
    cudaGetSymbolAddress((void**)&q,   g_q);
    cudaGetSymbolAddress((void**)&k,   g_k);
    cudaGetSymbolAddress((void**)&v,   g_v);
    cudaGetSymbolAddress((void**)&ctx, g_ctx);

    const int SMEM1 = (2 * 128 * SSTRIDE + 256) * 4;   // Qs + Ks + stats, ~70.7KB
    cudaFuncSetAttribute(scores_stats, cudaFuncAttributeMaxDynamicSharedMemorySize, SMEM1);

    dim3 gProj(DMODEL / 128, (BB * SEQ) / 128);        // (8, 32)

    proj_tf32<<<gProj, 256>>>(inputs_q,  Wq, bq, q, BB * SEQ, DMODEL, DMODEL);
    proj_tf32<<<gProj, 256>>>(inputs_kv, Wk, bk, k, BB * SEQ, DMODEL, DMODEL);
    proj_tf32<<<gProj, 256>>>(inputs_kv, Wv, bv, v, BB * SEQ, DMODEL, DMODEL);

    scores_stats<<<dim3(SEQ / 128, BB * NH), 256, SMEM1>>>(attn);

    ctx_fused2<<<dim3(SEQ / 128, BB * NH), 256>>>(attn);

    proj_tf32<<<gProj, 256>>>(ctx, Wo, bo, out, BB * SEQ, DMODEL, DMODEL);
}

// round 15
// speedup vs baseline: 1.1060x; 1.0017x over previous
#include <cuda_runtime.h>
#include <math.h>
#include <stdint.h>

#define BB 2
#define SEQ 2048
#define DMODEL 1024
#define NH 16
#define HD 64
#define QKV_ELEMS (BB * SEQ * DMODEL)

// Scratch (no allocations allowed)
__device__ float g_q[QKV_ELEMS];
__device__ float g_k[QKV_ELEMS];
__device__ float g_v[QKV_ELEMS];
__device__ float g_ctx[QKV_ELEMS];
__device__ float g_m[BB * NH * SEQ];
__device__ float g_l[BB * NH * SEQ];

__device__ __forceinline__ uint32_t f2tf(float x) {
    uint32_t r;
    asm("cvt.rna.tf32.f32 %0, %1;" : "=r"(r) : "f"(x));
    return r;
}

__device__ __forceinline__ void mma8(float* c, const uint32_t* a, const uint32_t* b) {
    asm volatile(
        "mma.sync.aligned.m16n8k8.row.col.f32.tf32.tf32.f32 "
        "{%0,%1,%2,%3},{%4,%5,%6,%7},{%8,%9},{%0,%1,%2,%3};"
        : "+f"(c[0]), "+f"(c[1]), "+f"(c[2]), "+f"(c[3])
        : "r"(a[0]), "r"(a[1]), "r"(a[2]), "r"(a[3]), "r"(b[0]), "r"(b[1]));
}

// ---------------------------------------------------------------------------
// Proj GEMM (NN): C[M,N] = A[M,K] @ B[K,N] + bias[N]  (R13, measured)
// ---------------------------------------------------------------------------
__global__ __launch_bounds__(256, 2) void proj_tf32(
    const float* __restrict__ A, const float* __restrict__ B,
    const float* __restrict__ bias, float* __restrict__ C,
    int M, int N, int K)
{
    __shared__ uint32_t As[128][20];
    __shared__ uint32_t Bs[16][136];

    const int tid = threadIdx.x;
    const int lane = tid & 31, wid = tid >> 5;
    const int rowBase = blockIdx.y * 128, colBase = blockIdx.x * 128;
    const int rowOff = (wid >> 1) * 32, colOff = (wid & 1) * 64;
    const int gp = lane >> 2, tig = lane & 3;

    const int ar0 = tid >> 2, ac4 = tid & 3;
    const int bk0 = tid >> 5, bn4 = tid & 31;

    const float* Abase = A + (size_t)rowBase * K;

    float4 aPre[2], bPre[2];
    aPre[0] = *(const float4*)(Abase + (size_t)ar0 * K + ac4 * 4);
    aPre[1] = *(const float4*)(Abase + (size_t)(ar0 + 64) * K + ac4 * 4);
    bPre[0] = *(const float4*)(B + (size_t)bk0 * N + colBase + bn4 * 4);
    bPre[1] = *(const float4*)(B + (size_t)(bk0 + 8) * N + colBase + bn4 * 4);

    float acc[2][8][4];
#pragma unroll
    for (int t = 0; t < 2; t++)
#pragma unroll
        for (int j = 0; j < 8; j++)
#pragma unroll
            for (int q = 0; q < 4; q++) acc[t][j][q] = 0.0f;

    const int KT = K / 16;
    for (int kt = 0; kt < KT; ++kt) {
        As[ar0][ac4 * 4 + 0] = f2tf(aPre[0].x);
        As[ar0][ac4 * 4 + 1] = f2tf(aPre[0].y);
        As[ar0][ac4 * 4 + 2] = f2tf(aPre[0].z);
        As[ar0][ac4 * 4 + 3] = f2tf(aPre[0].w);
        As[ar0 + 64][ac4 * 4 + 0] = f2tf(aPre[1].x);
        As[ar0 + 64][ac4 * 4 + 1] = f2tf(aPre[1].y);
        As[ar0 + 64][ac4 * 4 + 2] = f2tf(aPre[1].z);
        As[ar0 + 64][ac4 * 4 + 3] = f2tf(aPre[1].w);
        Bs[bk0][bn4 * 4 + 0] = f2tf(bPre[0].x);
        Bs[bk0][bn4 * 4 + 1] = f2tf(bPre[0].y);
        Bs[bk0][bn4 * 4 + 2] = f2tf(bPre[0].z);
        Bs[bk0][bn4 * 4 + 3] = f2tf(bPre[0].w);
        Bs[bk0 + 8][bn4 * 4 + 0] = f2tf(bPre[1].x);
        Bs[bk0 + 8][bn4 * 4 + 1] = f2tf(bPre[1].y);
        Bs[bk0 + 8][bn4 * 4 + 2] = f2tf(bPre[1].z);
        Bs[bk0 + 8][bn4 * 4 + 3] = f2tf(bPre[1].w);
        __syncthreads();

        if (kt + 1 < KT) {
            const float* Ak = Abase + (kt + 1) * 16;
            aPre[0] = *(const float4*)(Ak + (size_t)ar0 * K + ac4 * 4);
            aPre[1] = *(const float4*)(Ak + (size_t)(ar0 + 64) * K + ac4 * 4);
            bPre[0] = *(const float4*)(B + (size_t)((kt + 1) * 16 + bk0) * N + colBase + bn4 * 4);
            bPre[1] = *(const float4*)(B + (size_t)((kt + 1) * 16 + bk0 + 8) * N + colBase + bn4 * 4);
        }

#pragma unroll
        for (int ks = 0; ks < 2; ++ks) {
            uint32_t a[2][4];
#pragma unroll
            for (int t = 0; t < 2; t++) {
                int r = rowOff + t * 16 + gp;
                a[t][0] = As[r][ks * 8 + tig];
                a[t][1] = As[r + 8][ks * 8 + tig];
                a[t][2] = As[r][ks * 8 + tig + 4];
                a[t][3] = As[r + 8][ks * 8 + tig + 4];
            }
#pragma unroll
            for (int j = 0; j < 8; j++) {
                uint32_t b[2];
                int cb = colOff + j * 8 + gp;
                b[0] = Bs[ks * 8 + tig][cb];
                b[1] = Bs[ks * 8 + tig + 4][cb];
                mma8(acc[0][j], a[0], b);
                mma8(acc[1][j], a[1], b);
            }
        }
        __syncthreads();
    }

#pragma unroll
    for (int t = 0; t < 2; t++) {
#pragma unroll
        for (int j = 0; j < 8; j++) {
            int row = rowBase + rowOff + t * 16 + gp;
            int col = colBase + colOff + j * 8 + 2 * tig;
            float2 bb = *(const float2*)&bias[col];
            float2 r0, r1;
            r0.x = acc[t][j][0] + bb.x; r0.y = acc[t][j][1] + bb.y;
            r1.x = acc[t][j][2] + bb.x; r1.y = acc[t][j][3] + bb.y;
            *(float2*)&C[(size_t)row * N + col] = r0;
            *(float2*)&C[(size_t)(row + 8) * N + col] = r1;
        }
    }
}

// ---------------------------------------------------------------------------
// scores_stats v3 (R10/R13, measured ~190us)
// ---------------------------------------------------------------------------
#define SSTRIDE 68
__global__ __launch_bounds__(256, 2) void scores_stats(float* __restrict__ attn)
{
    extern __shared__ uint32_t sm1[];
    uint32_t* Qs = sm1;
    uint32_t* Ks = sm1 + 128 * SSTRIDE;
    float* sm_m = (float*)(sm1 + 2 * 128 * SSTRIDE);
    float* sm_l = sm_m + 128;

    const int tid = threadIdx.x;
    const int lane = tid & 31, wid = tid >> 5;
    const int warpM = wid >> 1, warpN = wid & 1;
    const int gp = lane >> 2, tig = lane & 3;
    const int z = blockIdx.y, b = z >> 4, h = z & 15;
    const int rowBase = blockIdx.x * 128;

    const float* Qb = g_q + (size_t)(b * SEQ) * DMODEL + h * HD;
    const float* Kb = g_k + (size_t)(b * SEQ) * DMODEL + h * HD;

#pragma unroll
    for (int i = 0; i < 8; i++) {
        int g = tid + i * 256;
        int r = g >> 4, c4 = g & 15;
        float4 qv = *(const float4*)(Qb + (size_t)(rowBase + r) * DMODEL + c4 * 4);
        uint32_t* qp = &Qs[r * SSTRIDE + c4 * 4];
        qp[0] = f2tf(qv.x * 0.125f); qp[1] = f2tf(qv.y * 0.125f);
        qp[2] = f2tf(qv.z * 0.125f); qp[3] = f2tf(qv.w * 0.125f);
    }

    float mP[2][2], lP[2][2];
#pragma unroll
    for (int t = 0; t < 2; t++)
#pragma unroll
        for (int hf = 0; hf < 2; hf++) { mP[t][hf] = -1e30f; lP[t][hf] = 0.0f; }

    for (int kc = 0; kc < 16; ++kc) {
        __syncthreads();
#pragma unroll
        for (int i = 0; i < 8; i++) {
            int g = tid + i * 256;
            int r = g >> 4, c4 = g & 15;
            float4 kv = *(const float4*)(Kb + (size_t)(kc * 128 + r) * DMODEL + c4 * 4);
            uint32_t* kp = &Ks[r * SSTRIDE + c4 * 4];
            kp[0] = f2tf(kv.x); kp[1] = f2tf(kv.y);
            kp[2] = f2tf(kv.z); kp[3] = f2tf(kv.w);
        }
        __syncthreads();

        float acc[2][8][4];
#pragma unroll
        for (int t = 0; t < 2; t++)
#pragma unroll
            for (int j = 0; j < 8; j++)
#pragma unroll
                for (int q = 0; q < 4; q++) acc[t][j][q] = 0.0f;

#pragma unroll
        for (int ks = 0; ks < 8; ++ks) {
            uint32_t a[2][4];
#pragma unroll
            for (int t = 0; t < 2; t++) {
                int r = warpM * 32 + t * 16 + gp;
                a[t][0] = Qs[r * SSTRIDE + ks * 8 + tig];
                a[t][1] = Qs[(r + 8) * SSTRIDE + ks * 8 + tig];
                a[t][2] = Qs[r * SSTRIDE + ks * 8 + tig + 4];
                a[t][3] = Qs[(r + 8) * SSTRIDE + ks * 8 + tig + 4];
            }
#pragma unroll
            for (int j = 0; j < 8; j++) {
                uint32_t b2[2];
                int n = warpN * 64 + j * 8 + gp;
                b2[0] = Ks[n * SSTRIDE + ks * 8 + tig];
                b2[1] = Ks[n * SSTRIDE + ks * 8 + tig + 4];
                mma8(acc[0][j], a[0], b2);
                mma8(acc[1][j], a[1], b2);
            }
        }

#pragma unroll
        for (int t = 0; t < 2; t++) {
            float tm0 = -1e30f, tm1 = -1e30f;
#pragma unroll
            for (int j = 0; j < 8; j++) {
                tm0 = fmaxf(tm0, fmaxf(acc[t][j][0], acc[t][j][1]));
                tm1 = fmaxf(tm1, fmaxf(acc[t][j][2], acc[t][j][3]));
            }
            tm0 = fmaxf(tm0, __shfl_xor_sync(0xffffffffu, tm0, 1));
            tm0 = fmaxf(tm0, __shfl_xor_sync(0xffffffffu, tm0, 2));
            tm1 = fmaxf(tm1, __shfl_xor_sync(0xffffffffu, tm1, 1));
            tm1 = fmaxf(tm1, __shfl_xor_sync(0xffffffffu, tm1, 2));
            float mn0 = fmaxf(mP[t][0], tm0), mn1 = fmaxf(mP[t][1], tm1);
            float ts0 = 0.0f, ts1 = 0.0f;
#pragma unroll
            for (int j = 0; j < 8; j++) {
                ts0 += expf(acc[t][j][0] - mn0) + expf(acc[t][j][1] - mn0);
                ts1 += expf(acc[t][j][2] - mn1) + expf(acc[t][j][3] - mn1);
            }
            ts0 += __shfl_xor_sync(0xffffffffu, ts0, 1);
            ts0 += __shfl_xor_sync(0xffffffffu, ts0, 2);
            ts1 += __shfl_xor_sync(0xffffffffu, ts1, 1);
            ts1 += __shfl_xor_sync(0xffffffffu, ts1, 2);
            lP[t][0] = lP[t][0] * expf(mP[t][0] - mn0) + ts0; mP[t][0] = mn0;
            lP[t][1] = lP[t][1] * expf(mP[t][1] - mn1) + ts1; mP[t][1] = mn1;
        }

#pragma unroll
        for (int t = 0; t < 2; t++) {
            int rowg = rowBase + warpM * 32 + t * 16 + gp;
            float* Crow0 = attn + (size_t)z * SEQ * SEQ + (size_t)rowg * SEQ + kc * 128 + warpN * 64;
            float* Crow1 = Crow0 + (size_t)8 * SEQ;
#pragma unroll
            for (int j = 0; j < 8; j++) {
                float2 v0, v1;
                v0.x = acc[t][j][0]; v0.y = acc[t][j][1];
                v1.x = acc[t][j][2]; v1.y = acc[t][j][3];
                *(float2*)(Crow0 + j * 8 + 2 * tig) = v0;
                *(float2*)(Crow1 + j * 8 + 2 * tig) = v1;
            }
        }
    }

    __syncthreads();
    if (warpN == 1 && tig == 0) {
#pragma unroll
        for (int t = 0; t < 2; t++)
#pragma unroll
            for (int hf = 0; hf < 2; hf++) {
                int rl = warpM * 32 + t * 16 + hf * 8 + gp;
                sm_m[rl] = mP[t][hf];
                sm_l[rl] = lP[t][hf];
            }
    }
    __syncthreads();
    if (warpN == 0 && tig == 0) {
#pragma unroll
        for (int t = 0; t < 2; t++)
#pragma unroll
            for (int hf = 0; hf < 2; hf++) {
                int rl = warpM * 32 + t * 16 + hf * 8 + gp;
                float ma = mP[t][hf], la = lP[t][hf];
                float mb = sm_m[rl],  lb = sm_l[rl];
                float mf = fmaxf(ma, mb);
                float lf = la * expf(ma - mf) + lb * expf(mb - mf);
                g_m[(size_t)z * SEQ + rowBase + rl] = mf;
                g_l[(size_t)z * SEQ + rowBase + rl] = lf;
            }
    }
}

// ---------------------------------------------------------------------------
// ctx_fused3: double-buffered Ps/Vs (dynamic smem), ONE sync per 32-K tile.
// Loop: LDG next tile -> mma(cur buf) -> exp/P-write/STS(next buf) -> sync.
// ---------------------------------------------------------------------------
#define CPS 36
#define CVS 72
#define CTX_SMEM ((2 * 128 * CPS + 2 * 32 * CVS) * 4)
__global__ __launch_bounds__(256, 2) void ctx_fused3(float* __restrict__ attn)
{
    extern __shared__ uint32_t smc[];
    // Ps buf b: smc + b*128*CPS ; Vs buf b: smc + 2*128*CPS + b*32*CVS

    const int tid = threadIdx.x;
    const int lane = tid & 31, wid = tid >> 5;
    const int warpM = wid >> 1, warpN = wid & 1;
    const int gp = lane >> 2, tig = lane & 3;
    const int z = blockIdx.y, b = z >> 4, h = z & 15;
    const int rowBase = blockIdx.x * 128;

    float* P = attn + (size_t)z * SEQ * SEQ;
    const float* V = g_v + (size_t)b * SEQ * DMODEL + h * HD;

    const int sr = tid >> 3, sc4 = tid & 7;        // staging: 2 rows per thread pair? no: r = g>>3
    float mR[4], ilR[4];
#pragma unroll
    for (int i = 0; i < 4; i++) {
        int r = (tid + i * 256) >> 3;
        mR[i]  = g_m[(size_t)z * SEQ + rowBase + r];
        ilR[i] = 1.0f / g_l[(size_t)z * SEQ + rowBase + r];
    }
    (void)sr; (void)sc4;

    float acc[2][4][4];
#pragma unroll
    for (int t = 0; t < 2; t++)
#pragma unroll
        for (int j = 0; j < 4; j++)
#pragma unroll
            for (int q = 0; q < 4; q++) acc[t][j][q] = 0.0f;

    float4 pPre[4], vPre[2];

    // ---- prologue: stage tile 0 into buf 0 ----
#pragma unroll
    for (int i = 0; i < 4; i++) {
        int g = tid + i * 256;
        int r = g >> 3, c4 = g & 7;
        pPre[i] = *(const float4*)(P + (size_t)(rowBase + r) * SEQ + c4 * 4);
    }
#pragma unroll
    for (int i = 0; i < 2; i++) {
        int g = tid + i * 256;
        int k = g >> 4, n4 = g & 15;
        vPre[i] = *(const float4*)(V + (size_t)k * DMODEL + n4 * 4);
    }
    {
        uint32_t* Ps0 = smc;
        uint32_t* Vs0 = smc + 2 * 128 * CPS;
#pragma unroll
        for (int i = 0; i < 4; i++) {
            int g = tid + i * 256;
            int r = g >> 3, c4 = g & 7;
            float4 v = pPre[i];
            float4 p;
            p.x = expf(v.x - mR[i]) * ilR[i];
            p.y = expf(v.y - mR[i]) * ilR[i];
            p.z = expf(v.z - mR[i]) * ilR[i];
            p.w = expf(v.w - mR[i]) * ilR[i];
            *(float4*)(P + (size_t)(rowBase + r) * SEQ + c4 * 4) = p;
            uint32_t* pp = &Ps0[r * CPS + c4 * 4];
            pp[0] = f2tf(p.x); pp[1] = f2tf(p.y);
            pp[2] = f2tf(p.z); pp[3] = f2tf(p.w);
        }
#pragma unroll
        for (int i = 0; i < 2; i++) {
            int g = tid + i * 256;
            int k = g >> 4, n4 = g & 15;
            uint32_t* vp = &Vs0[k * CVS + n4 * 4];
            vp[0] = f2tf(vPre[i].x); vp[1] = f2tf(vPre[i].y);
            vp[2] = f2tf(vPre[i].z); vp[3] = f2tf(vPre[i].w);
        }
    }
    __syncthreads();

    const int KT = SEQ / 32;   // 64
    for (int kt = 0; kt < KT; ++kt) {
        const int cur = kt & 1;
        const bool more = (kt + 1 < KT);

        // issue next-tile gmem loads first (long latency, no smem deps)
        if (more) {
            const int k0 = (kt + 1) * 32;
#pragma unroll
            for (int i = 0; i < 4; i++) {
                int g = tid + i * 256;
                int r = g >> 3, c4 = g & 7;
                pPre[i] = *(const float4*)(P + (size_t)(rowBase + r) * SEQ + k0 + c4 * 4);
            }
#pragma unroll
            for (int i = 0; i < 2; i++) {
                int g = tid + i * 256;
                int k = g >> 4, n4 = g & 15;
                vPre[i] = *(const float4*)(V + (size_t)(k0 + k) * DMODEL + n4 * 4);
            }
        }

        // mma on current buffer
        {
            const uint32_t* Psc = smc + cur * 128 * CPS;
            const uint32_t* Vsc = smc + 2 * 128 * CPS + cur * 32 * CVS;
#pragma unroll
            for (int ks = 0; ks < 4; ++ks) {
                uint32_t a[2][4];
#pragma unroll
                for (int t = 0; t < 2; t++) {
                    int r = warpM * 32 + t * 16 + gp;
                    a[t][0] = Psc[r * CPS + ks * 8 + tig];
                    a[t][1] = Psc[(r + 8) * CPS + ks * 8 + tig];
                    a[t][2] = Psc[r * CPS + ks * 8 + tig + 4];
                    a[t][3] = Psc[(r + 8) * CPS + ks * 8 + tig + 4];
                }
#pragma unroll
                for (int j = 0; j < 4; j++) {
                    uint32_t b2[2];
                    int cb = warpN * 32 + j * 8 + gp;
                    b2[0] = Vsc[(ks * 8 + tig) * CVS + cb];
                    b2[1] = Vsc[(ks * 8 + tig + 4) * CVS + cb];
                    mma8(acc[0][j], a[0], b2);
                    mma8(acc[1][j], a[1], b2);
                }
            }
        }

        // stage next tile into other buffer (exp + P writeback + tf32 store)
        if (more) {
            const int k0 = (kt + 1) * 32;
            uint32_t* Psn = smc + (cur ^ 1) * 128 * CPS;
            uint32_t* Vsn = smc + 2 * 128 * CPS + (cur ^ 1) * 32 * CVS;
#pragma unroll
            for (int i = 0; i < 4; i++) {
                int g = tid + i * 256;
                int r = g >> 3, c4 = g & 7;
                float4 v = pPre[i];
                float4 p;
                p.x = expf(v.x - mR[i]) * ilR[i];
                p.y = expf(v.y - mR[i]) * ilR[i];
                p.z = expf(v.z - mR[i]) * ilR[i];
                p.w = expf(v.w - mR[i]) * ilR[i];
                *(float4*)(P + (size_t)(rowBase + r) * SEQ + k0 + c4 * 4) = p;
                uint32_t* pp = &Psn[r * CPS + c4 * 4];
                pp[0] = f2tf(p.x); pp[1] = f2tf(p.y);
                pp[2] = f2tf(p.z); pp[3] = f2tf(p.w);
            }
#pragma unroll
            for (int i = 0; i < 2; i++) {
                int g = tid + i * 256;
                int k = g >> 4, n4 = g & 15;
                uint32_t* vp = &Vsn[k * CVS + n4 * 4];
                vp[0] = f2tf(vPre[i].x); vp[1] = f2tf(vPre[i].y);
                vp[2] = f2tf(vPre[i].z); vp[3] = f2tf(vPre[i].w);
            }
        }
        __syncthreads();
    }

#pragma unroll
    for (int t = 0; t < 2; t++) {
#pragma unroll
        for (int j = 0; j < 4; j++) {
            int row = rowBase + warpM * 32 + t * 16 + gp;
            int col = warpN * 32 + j * 8 + 2 * tig;
            float* dst0 = g_ctx + (size_t)(b * SEQ + row) * DMODEL + h * HD + col;
            float* dst1 = g_ctx + (size_t)(b * SEQ + row + 8) * DMODEL + h * HD + col;
            float2 r0, r1;
            r0.x = acc[t][j][0]; r0.y = acc[t][j][1];
            r1.x = acc[t][j][2]; r1.y = acc[t][j][3];
            *(float2*)dst0 = r0;
            *(float2*)dst1 = r1;
        }
    }
}

// ---------------------------------------------------------------------------
extern "C" void kernel_launch(void* const* d_in, const int* in_sizes, int n_in,
                              void* d_out, int out_size)
{
    const float* inputs_q  = (const float*)d_in[0];
    const float* inputs_kv = (const float*)d_in[1];
    const float* Wq = (const float*)d_in[2];
    const float* bq = (const float*)d_in[3];
    const float* Wk = (const float*)d_in[4];
    const float* bk = (const float*)d_in[5];
    const float* Wv = (const float*)d_in[6];
    const float* bv = (const float*)d_in[7];
    const float* Wo = (const float*)d_in[8];
    const float* bo = (const float*)d_in[9];

    float* out  = (float*)d_out;                       // [B,SQ,D]
    float* attn = out + (size_t)BB * SEQ * DMODEL;     // [B,H,SQ,SKV]

    float *q, *k, *v, *ctx;
    cudaGetSymbolAddress((void**)&q,   g_q);
    cudaGetSymbolAddress((void**)&k,   g_k);
    cudaGetSymbolAddress((void**)&v,   g_v);
    cudaGetSymbolAddress((void**)&ctx, g_ctx);

    const int SMEM1 = (2 * 128 * SSTRIDE + 256) * 4;
    cudaFuncSetAttribute(scores_stats, cudaFuncAttributeMaxDynamicSharedMemorySize, SMEM1);
    cudaFuncSetAttribute(ctx_fused3,   cudaFuncAttributeMaxDynamicSharedMemorySize, CTX_SMEM);

    dim3 gProj(DMODEL / 128, (BB * SEQ) / 128);        // (8, 32)

    proj_tf32<<<gProj, 256>>>(inputs_q,  Wq, bq, q, BB * SEQ, DMODEL, DMODEL);
    proj_tf32<<<gProj, 256>>>(inputs_kv, Wk, bk, k, BB * SEQ, DMODEL, DMODEL);
    proj_tf32<<<gProj, 256>>>(inputs_kv, Wv, bv, v, BB * SEQ, DMODEL, DMODEL);

    scores_stats<<<dim3(SEQ / 128, BB * NH), 256, SMEM1>>>(attn);

    ctx_fused3<<<dim3(SEQ / 128, BB * NH), 256, CTX_SMEM>>>(attn);

    proj_tf32<<<gProj, 256>>>(ctx, Wo, bo, out, BB * SEQ, DMODEL, DMODEL);
}